// round 16
// baseline (speedup 1.0000x reference)
#include <cuda_runtime.h>
#include <cuda_bf16.h>
#include <cuda_fp16.h>
#include <stdint.h>
#include <math.h>

#define BB 2
#define SS 2048
#define HH 2048
#define NH 16
#define NKV 4
#define HD 128
#define NQKV 3072
#define RSCALE 0.08838834764831845f

// ---------------- scratch (device globals: allocation-free) ----------------
__device__ __half g_hs_hi[(size_t)BB * SS * HH];
__device__ __half g_qkvw_hi[(size_t)NQKV * HH];
__device__ __half g_ow_hi[(size_t)HH * NH * HD];
__device__ __half g_qhi[(size_t)BB * SS * NH * HD];
__device__ __half g_kh[(size_t)BB * SS * NKV * HD];
__device__ __half g_vh[(size_t)BB * SS * NKV * HD];
__device__ __half g_ahi[(size_t)BB * SS * NH * HD];
__device__ float g_cos[(size_t)SS * 64];
__device__ float g_sin[(size_t)SS * 64];

// ===================== warp-MMA helpers =====================
__device__ __forceinline__ uint32_t smem_to_u32(const void* p) {
    uint32_t a;
    asm("{ .reg .u64 t; cvta.to.shared.u64 t, %1; cvt.u32.u64 %0, t; }"
        : "=r"(a) : "l"(p));
    return a;
}
__device__ __forceinline__ void ldsm_x4(uint32_t r[4], uint32_t addr) {
    asm volatile("ldmatrix.sync.aligned.m8n8.x4.shared.b16 {%0,%1,%2,%3}, [%4];"
                 : "=r"(r[0]), "=r"(r[1]), "=r"(r[2]), "=r"(r[3]) : "r"(addr));
}
__device__ __forceinline__ void ldsm_x4_t(uint32_t r[4], uint32_t addr) {
    asm volatile("ldmatrix.sync.aligned.m8n8.x4.trans.shared.b16 {%0,%1,%2,%3}, [%4];"
                 : "=r"(r[0]), "=r"(r[1]), "=r"(r[2]), "=r"(r[3]) : "r"(addr));
}
__device__ __forceinline__ void mma16816h(float c[4], const uint32_t a[4],
                                          const uint32_t b0, const uint32_t b1) {
    asm volatile(
        "mma.sync.aligned.m16n8k16.row.col.f32.f16.f16.f32 "
        "{%0,%1,%2,%3}, {%4,%5,%6,%7}, {%8,%9}, {%0,%1,%2,%3};"
        : "+f"(c[0]), "+f"(c[1]), "+f"(c[2]), "+f"(c[3])
        : "r"(a[0]), "r"(a[1]), "r"(a[2]), "r"(a[3]), "r"(b0), "r"(b1));
}
__device__ __forceinline__ void cp_async16(uint32_t dst, const void* src) {
    asm volatile("cp.async.cg.shared.global [%0], [%1], 16;"
                 :: "r"(dst), "l"(src) : "memory");
}
#define CP_COMMIT() asm volatile("cp.async.commit_group;" ::: "memory")
#define CP_WAIT(n)  asm volatile("cp.async.wait_group %0;" :: "n"(n) : "memory")

__device__ __forceinline__ uint32_t pack2h(float x, float y) {
    return (uint32_t)__half_as_ushort(__float2half_rn(x))
         | ((uint32_t)__half_as_ushort(__float2half_rn(y)) << 16);
}
__device__ __forceinline__ uint32_t swz(int row, int c) {
    return (uint32_t)(row * 64 + ((c ^ ((row >> 1) & 3)) << 4));
}
__device__ __forceinline__ uint32_t swz256(int row, int c) {
    return (uint32_t)(row * 256 + ((c ^ (row & 7)) << 4));
}

// ---------------------------------------------------------------------------
// RoPE cos/sin table (same expf/sincosf expressions as before -> identical bits)
// ---------------------------------------------------------------------------
__global__ void rope_table(float* __restrict__ cost, float* __restrict__ sint)
{
    const int s = blockIdx.x, i = threadIdx.x;
    float inv_freq = expf(-(float)i * (13.122363377404328f / 64.0f));
    float ang = (float)s * inv_freq;
    float sn, cs;
    sincosf(ang, &sn, &cs);
    cost[s * 64 + i] = cs;
    sint[s * 64 + i] = sn;
}

// ---------------------------------------------------------------------------
// fused converter: one launch, all 5 fp32->fp16 converts.
// ---------------------------------------------------------------------------
__global__ void conv_all(const float* __restrict__ hs,
                         const float* __restrict__ qw, const float* __restrict__ kw,
                         const float* __restrict__ vw, const float* __restrict__ ow,
                         __half* __restrict__ hsh,
                         __half* __restrict__ qkvw, __half* __restrict__ owh)
{
    const int blk = blockIdx.x;
    const float* src;
    __half* dst;
    int base;
    if (blk < 8192)       { src = hs; dst = hsh;                       base = blk; }
    else if (blk < 12288) { src = qw; dst = qkvw;                      base = blk - 8192; }
    else if (blk < 13312) { src = kw; dst = qkvw + (size_t)2048 * HH;  base = blk - 12288; }
    else if (blk < 14336) { src = vw; dst = qkvw + (size_t)2560 * HH;  base = blk - 13312; }
    else                  { src = ow; dst = owh;                       base = blk - 14336; }
    size_t i = ((size_t)base * 256 + threadIdx.x) * 4;
    float4 f = *(const float4*)(src + i);
    uint2 h;
    h.x = pack2h(f.x, f.y);
    h.y = pack2h(f.z, f.w);
    *(uint2*)(dst + i) = h;
}

// ---------------------------------------------------------------------------
// QKV GEMM with FUSED rmsnorm+RoPE+fp16 epilogue.
// C-tile column block == one head: nb<16 Q, 16..19 K, 20..23 V.
// BM=BN=128, BK=32, 512 threads (16 warps 4x4). 4-stage cp.async pipeline.
// ---------------------------------------------------------------------------
#define GS_AH 0
#define GS_BH 8192
#define GS_STAGE 16384
#define QKV_SMEM 67584     // max(4*16384, 128*132*4)

__global__ void __launch_bounds__(512) gemm_qkv(
    const __half* __restrict__ Ahi, const __half* __restrict__ Bhi,
    const float* __restrict__ qn, const float* __restrict__ kn,
    const float* __restrict__ cost, const float* __restrict__ sint,
    __half* __restrict__ qhi, __half* __restrict__ khv, __half* __restrict__ vhv)
{
    extern __shared__ char smem[];
    const uint32_t sb = smem_to_u32(smem);
    const int K = HH;

    const int t = threadIdx.x;
    const int lane = t & 31, wid = t >> 5;
    const int bm = blockIdx.y * 128, bn = blockIdx.x * 128;
    const int wm = (wid & 3) * 32;
    const int wn = (wid >> 2) * 32;

    const int lrow = t >> 2, lc = t & 3;
    const size_t ga = (size_t)(bm + lrow) * K + lc * 8;
    const size_t gb = (size_t)(bn + lrow) * K + lc * 8;
    const uint32_t st = swz(lrow, lc);
    const int nch = K >> 5;

    auto issue = [&](int ch) {
        uint32_t base = sb + (uint32_t)(ch & 3) * GS_STAGE + st;
        cp_async16(base + GS_AH, Ahi + ga + (size_t)ch * 32);
        cp_async16(base + GS_BH, Bhi + gb + (size_t)ch * 32);
    };

    issue(0); CP_COMMIT();
    issue(1); CP_COMMIT();
    issue(2); CP_COMMIT();

    float acc[2][4][4];
#pragma unroll
    for (int i = 0; i < 2; i++)
#pragma unroll
        for (int j = 0; j < 4; j++)
#pragma unroll
            for (int q = 0; q < 4; q++) acc[i][j][q] = 0.0f;

    for (int ch = 0; ch < nch; ch++) {
        CP_WAIT(2);
        __syncthreads();
        if (ch + 3 < nch) issue(ch + 3);
        CP_COMMIT();                              // unconditional (tail safety)

        const uint32_t base = sb + (uint32_t)(ch & 3) * GS_STAGE;
#pragma unroll
        for (int ks = 0; ks < 2; ks++) {
            uint32_t ah[2][4];
#pragma unroll
            for (int mt = 0; mt < 2; mt++) {
                int row = wm + mt * 16 + (lane & 15);
                int c = ks * 2 + (lane >> 4);
                ldsm_x4(ah[mt], base + GS_AH + swz(row, c));
            }
#pragma unroll
            for (int np = 0; np < 2; np++) {
                uint32_t bh[4];
                int row = wn + np * 16 + (lane & 7) + ((lane >> 4) & 1) * 8;
                int c = ks * 2 + ((lane >> 3) & 1);
                ldsm_x4(bh, base + GS_BH + swz(row, c));
#pragma unroll
                for (int half = 0; half < 2; half++) {
                    int nt = np * 2 + half, pb = half * 2;
#pragma unroll
                    for (int mt = 0; mt < 2; mt++)
                        mma16816h(acc[mt][nt], ah[mt], bh[pb], bh[pb + 1]);
                }
            }
        }
    }

    // ---- fused epilogue: stage fp32 tile, rmsnorm+rope, emit fp16 ----
    CP_WAIT(0);
    __syncthreads();                  // pipeline smem now reusable as stage
    float* stage = (float*)smem;      // [128][132]
#pragma unroll
    for (int mt = 0; mt < 2; mt++)
#pragma unroll
        for (int nt = 0; nt < 4; nt++) {
            int r = wm + mt * 16 + (lane >> 2);
            int c = wn + nt * 8 + (lane & 3) * 2;
            *(float2*)&stage[r * 132 + c] = make_float2(acc[mt][nt][0], acc[mt][nt][1]);
            *(float2*)&stage[(r + 8) * 132 + c] = make_float2(acc[mt][nt][2], acc[mt][nt][3]);
        }
    __syncthreads();

    const int nb = blockIdx.x;        // 0..23
    const int row = t >> 2, q = t & 3;
    const int grow = bm + row;
    const int s = grow & (SS - 1);
    const float* srow = &stage[row * 132];

    if (nb >= 20) {
        // V: plain fp16 convert
        __half* dst = vhv + ((size_t)grow * NKV + (nb - 20)) * HD + q * 32;
#pragma unroll
        for (int j = 0; j < 32; j += 2)
            *(uint32_t*)&dst[j] = pack2h(srow[q * 32 + j], srow[q * 32 + j + 1]);
        return;
    }

    const bool isQ = (nb < 16);
    const float* w = isQ ? qn : kn;
    const float prescale = isQ ? RSCALE : 1.0f;

    float ss = 0.0f;
#pragma unroll
    for (int j = 0; j < 32; j++) {
        float x = srow[q * 32 + j];
        ss += x * x;
    }
    ss += __shfl_xor_sync(0xffffffffu, ss, 1);
    ss += __shfl_xor_sync(0xffffffffu, ss, 2);
    float rs = rsqrtf(ss * (1.0f / 128.0f) + 1e-5f);

    __half* dst = isQ ? (qhi + ((size_t)grow * NH + nb) * HD)
                      : (khv + ((size_t)grow * NKV + (nb - 16)) * HD);
    const float* cr = cost + (size_t)s * 64;
    const float* sr = sint + (size_t)s * 64;
#pragma unroll
    for (int j = 0; j < 32; j += 2) {
        float r2[2];
#pragma unroll
        for (int u = 0; u < 2; u++) {
            int d = q * 32 + j + u;
            float xn = srow[d] * rs * w[d];
            float xo = srow[d ^ 64] * rs * w[d ^ 64];
            int i = d & 63;
            float res = (d < 64) ? (xn * cr[i] - xo * sr[i])
                                 : (xn * cr[i] + xo * sr[i]);
            r2[u] = res * prescale;
        }
        *(uint32_t*)&dst[q * 32 + j] = pack2h(r2[0], r2[1]);
    }
}

// ---------------------------------------------------------------------------
// fp16 1-pass GEMM (O projection): C[M][N] = Ahi[M][K] * Bhi[N][K]^T (fp32 out)
// ---------------------------------------------------------------------------
#define GS_SMEM (4 * GS_STAGE)

__global__ void __launch_bounds__(512) gemm_fp16(
    const __half* __restrict__ Ahi, const __half* __restrict__ Bhi,
    float* __restrict__ C, int M, int N, int K)
{
    extern __shared__ char smem[];
    const uint32_t sb = smem_to_u32(smem);

    const int t = threadIdx.x;
    const int lane = t & 31, wid = t >> 5;
    const int bm = blockIdx.y * 128, bn = blockIdx.x * 128;
    const int wm = (wid & 3) * 32;
    const int wn = (wid >> 2) * 32;

    const int lrow = t >> 2, lc = t & 3;
    const size_t ga = (size_t)(bm + lrow) * K + lc * 8;
    const size_t gb = (size_t)(bn + lrow) * K + lc * 8;
    const uint32_t st = swz(lrow, lc);
    const int nch = K >> 5;

    auto issue = [&](int ch) {
        uint32_t base = sb + (uint32_t)(ch & 3) * GS_STAGE + st;
        cp_async16(base + GS_AH, Ahi + ga + (size_t)ch * 32);
        cp_async16(base + GS_BH, Bhi + gb + (size_t)ch * 32);
    };

    issue(0); CP_COMMIT();
    issue(1); CP_COMMIT();
    issue(2); CP_COMMIT();

    float acc[2][4][4];
#pragma unroll
    for (int i = 0; i < 2; i++)
#pragma unroll
        for (int j = 0; j < 4; j++)
#pragma unroll
            for (int q = 0; q < 4; q++) acc[i][j][q] = 0.0f;

    for (int ch = 0; ch < nch; ch++) {
        CP_WAIT(2);
        __syncthreads();
        if (ch + 3 < nch) issue(ch + 3);
        CP_COMMIT();                              // unconditional (tail safety)

        const uint32_t base = sb + (uint32_t)(ch & 3) * GS_STAGE;
#pragma unroll
        for (int ks = 0; ks < 2; ks++) {
            uint32_t ah[2][4];
#pragma unroll
            for (int mt = 0; mt < 2; mt++) {
                int row = wm + mt * 16 + (lane & 15);
                int c = ks * 2 + (lane >> 4);
                ldsm_x4(ah[mt], base + GS_AH + swz(row, c));
            }
#pragma unroll
            for (int np = 0; np < 2; np++) {
                uint32_t bh[4];
                int row = wn + np * 16 + (lane & 7) + ((lane >> 4) & 1) * 8;
                int c = ks * 2 + ((lane >> 3) & 1);
                ldsm_x4(bh, base + GS_BH + swz(row, c));
#pragma unroll
                for (int half = 0; half < 2; half++) {
                    int nt = np * 2 + half, pb = half * 2;
#pragma unroll
                    for (int mt = 0; mt < 2; mt++)
                        mma16816h(acc[mt][nt], ah[mt], bh[pb], bh[pb + 1]);
                }
            }
        }
    }

#pragma unroll
    for (int mt = 0; mt < 2; mt++)
#pragma unroll
        for (int nt = 0; nt < 4; nt++) {
            int r0 = bm + wm + mt * 16 + (lane >> 2);
            int c0 = bn + wn + nt * 8 + (lane & 3) * 2;
            float2 v0 = make_float2(acc[mt][nt][0], acc[mt][nt][1]);
            float2 v1 = make_float2(acc[mt][nt][2], acc[mt][nt][3]);
            *(float2*)&C[(size_t)r0 * N + c0] = v0;
            *(float2*)&C[(size_t)(r0 + 8) * N + c0] = v1;
        }
}

// ---------------------------------------------------------------------------
// Tensor-core causal flash attention, GQA — fully fp16 1-pass.
// BM=64 per CTA, 128 threads (4 warps) -> 2 CTAs/SM. Q frags in registers.
// ---------------------------------------------------------------------------
#define ST_KH 0
#define ST_VH 16384
#define KV_STAGE 32768
#define FL_SMEM (2 * KV_STAGE)

__global__ void __launch_bounds__(128) flash_attn_tc(
    const __half* __restrict__ qhi,
    const __half* __restrict__ kh, const __half* __restrict__ vh,
    __half* __restrict__ ohi)
{
    extern __shared__ char smem[];
    const uint32_t sb = smem_to_u32(smem);
    const int t = threadIdx.x, lane = t & 31, wid = t >> 5;
    const int qb = gridDim.x - 1 - blockIdx.x;
    const int h = blockIdx.y, b = blockIdx.z;
    const int kvh = h >> 2;
    const int warp_m = wid * 16;
    const int QSTR = NH * HD;
    const int KSTR = NKV * HD;

    {
        const __half* qh = qhi + ((size_t)(b * SS + qb * 64)) * QSTR + h * HD;
#pragma unroll
        for (int i = 0; i < 8; i++) {
            int u = t + i * 128;
            int r = u >> 4, c = u & 15;
            *(uint4*)(smem + swz256(r, c)) =
                *(const uint4*)(qh + (size_t)r * QSTR + c * 8);
        }
    }
    __syncthreads();
    uint32_t qf[8][4];
#pragma unroll
    for (int ks = 0; ks < 8; ks++) {
        int ar = warp_m + (lane & 15);
        int ac = ks * 2 + (lane >> 4);
        ldsm_x4(qf[ks], sb + swz256(ar, ac));
    }
    __syncthreads();

    const int cr = t >> 4, cc = t & 15;
    const __half* kh0 = kh + ((size_t)(b * SS)) * KSTR + kvh * HD;
    const __half* vh0 = vh + ((size_t)(b * SS)) * KSTR + kvh * HD;

    auto issue_kv = [&](int kb) {
        uint32_t stage = sb + (uint32_t)(kb & 1) * KV_STAGE;
#pragma unroll
        for (int i = 0; i < 8; i++) {
            int r = cr + i * 8;
            size_t g = (size_t)(kb * 64 + r) * KSTR + cc * 8;
            uint32_t s = swz256(r, cc);
            cp_async16(stage + ST_KH + s, kh0 + g);
            cp_async16(stage + ST_VH + s, vh0 + g);
        }
    };

    issue_kv(0); CP_COMMIT();

    float m0 = -INFINITY, m1 = -INFINITY, l0 = 0.0f, l1 = 0.0f;
    float oacc[16][4];
#pragma unroll
    for (int i = 0; i < 16; i++)
#pragma unroll
        for (int j = 0; j < 4; j++) oacc[i][j] = 0.0f;

    const int row_lo = qb * 64 + warp_m + (lane >> 2);
    const int nkb = qb + 1;

    for (int kb = 0; kb < nkb; kb++) {
        CP_WAIT(0);
        __syncthreads();
        if (kb + 1 < nkb) { issue_kv(kb + 1); CP_COMMIT(); }

        const bool need_mask = (kb == qb);
        const uint32_t stage = sb + (uint32_t)(kb & 1) * KV_STAGE;

        float sacc[8][4];
#pragma unroll
        for (int i = 0; i < 8; i++)
#pragma unroll
            for (int j = 0; j < 4; j++) sacc[i][j] = 0.0f;

#pragma unroll
        for (int ks = 0; ks < 8; ks++) {
#pragma unroll
            for (int np = 0; np < 4; np++) {
                uint32_t bh[4];
                int br = np * 16 + (lane & 7) + ((lane >> 4) & 1) * 8;
                int bc = ks * 2 + ((lane >> 3) & 1);
                ldsm_x4(bh, stage + ST_KH + swz256(br, bc));
                mma16816h(sacc[np * 2 + 0], qf[ks], bh[0], bh[1]);
                mma16816h(sacc[np * 2 + 1], qf[ks], bh[2], bh[3]);
            }
        }

        if (need_mask) {
#pragma unroll
            for (int nt = 0; nt < 8; nt++) {
                int col = kb * 64 + nt * 8 + (lane & 3) * 2;
#pragma unroll
                for (int j = 0; j < 4; j++) {
                    int cc2 = col + (j & 1);
                    int rr = row_lo + ((j >> 1) << 3);
                    if (cc2 > rr) sacc[nt][j] = -INFINITY;
                }
            }
        }

        float mt0 = -INFINITY, mt1 = -INFINITY;
#pragma unroll
        for (int nt = 0; nt < 8; nt++) {
            mt0 = fmaxf(mt0, fmaxf(sacc[nt][0], sacc[nt][1]));
            mt1 = fmaxf(mt1, fmaxf(sacc[nt][2], sacc[nt][3]));
        }
        mt0 = fmaxf(mt0, __shfl_xor_sync(0xffffffffu, mt0, 1));
        mt0 = fmaxf(mt0, __shfl_xor_sync(0xffffffffu, mt0, 2));
        mt1 = fmaxf(mt1, __shfl_xor_sync(0xffffffffu, mt1, 1));
        mt1 = fmaxf(mt1, __shfl_xor_sync(0xffffffffu, mt1, 2));

        float mn0 = fmaxf(m0, mt0), mn1 = fmaxf(m1, mt1);
        float sc0 = __expf(m0 - mn0), sc1 = __expf(m1 - mn1);
        m0 = mn0; m1 = mn1;

        float ps0 = 0.0f, ps1 = 0.0f;
#pragma unroll
        for (int nt = 0; nt < 8; nt++) {
            sacc[nt][0] = __expf(sacc[nt][0] - mn0);
            sacc[nt][1] = __expf(sacc[nt][1] - mn0);
            sacc[nt][2] = __expf(sacc[nt][2] - mn1);
            sacc[nt][3] = __expf(sacc[nt][3] - mn1);
            ps0 += sacc[nt][0] + sacc[nt][1];
            ps1 += sacc[nt][2] + sacc[nt][3];
        }
        ps0 += __shfl_xor_sync(0xffffffffu, ps0, 1);
        ps0 += __shfl_xor_sync(0xffffffffu, ps0, 2);
        ps1 += __shfl_xor_sync(0xffffffffu, ps1, 1);
        ps1 += __shfl_xor_sync(0xffffffffu, ps1, 2);
        l0 = l0 * sc0 + ps0;
        l1 = l1 * sc1 + ps1;

#pragma unroll
        for (int nt = 0; nt < 16; nt++) {
            oacc[nt][0] *= sc0; oacc[nt][1] *= sc0;
            oacc[nt][2] *= sc1; oacc[nt][3] *= sc1;
        }

#pragma unroll
        for (int ks = 0; ks < 4; ks++) {
            uint32_t phi[4];
            phi[0] = pack2h(sacc[2 * ks][0], sacc[2 * ks][1]);
            phi[1] = pack2h(sacc[2 * ks][2], sacc[2 * ks][3]);
            phi[2] = pack2h(sacc[2 * ks + 1][0], sacc[2 * ks + 1][1]);
            phi[3] = pack2h(sacc[2 * ks + 1][2], sacc[2 * ks + 1][3]);
#pragma unroll
            for (int dp = 0; dp < 8; dp++) {
                uint32_t vh4[4];
                int vr = ks * 16 + (lane & 7) + ((lane >> 3) & 1) * 8;
                int vc = dp * 2 + (lane >> 4);
                ldsm_x4_t(vh4, stage + ST_VH + swz256(vr, vc));
                mma16816h(oacc[dp * 2], phi, vh4[0], vh4[1]);
                mma16816h(oacc[dp * 2 + 1], phi, vh4[2], vh4[3]);
            }
        }
    }

    float il0 = 1.0f / l0, il1 = 1.0f / l1;
    __half* oh = ohi + ((size_t)(b * SS)) * QSTR + h * HD;
    int r0 = qb * 64 + warp_m + (lane >> 2);
#pragma unroll
    for (int nt = 0; nt < 16; nt++) {
        int dim = nt * 8 + (lane & 3) * 2;
        uint32_t h0 = pack2h(oacc[nt][0] * il0, oacc[nt][1] * il0);
        uint32_t h1 = pack2h(oacc[nt][2] * il1, oacc[nt][3] * il1);
        *(uint32_t*)&oh[(size_t)r0 * QSTR + dim] = h0;
        *(uint32_t*)&oh[(size_t)(r0 + 8) * QSTR + dim] = h1;
    }
}

// ---------------------------------------------------------------------------
extern "C" void kernel_launch(void* const* d_in, const int* in_sizes, int n_in,
                              void* d_out, int out_size)
{
    const float* hs  = (const float*)d_in[0];
    const float* q_w = (const float*)d_in[1];
    const float* k_w = (const float*)d_in[2];
    const float* v_w = (const float*)d_in[3];
    const float* o_w = (const float*)d_in[4];
    const float* qn  = (const float*)d_in[5];
    const float* kn  = (const float*)d_in[6];
    float* out = (float*)d_out;

    __half *hsh, *qkvw, *owh, *pah, *pqh, *pkh, *pvh;
    float *pcos, *psin;
    cudaGetSymbolAddress((void**)&hsh, g_hs_hi);
    cudaGetSymbolAddress((void**)&qkvw, g_qkvw_hi);
    cudaGetSymbolAddress((void**)&owh, g_ow_hi);
    cudaGetSymbolAddress((void**)&pah, g_ahi);
    cudaGetSymbolAddress((void**)&pqh, g_qhi);
    cudaGetSymbolAddress((void**)&pkh, g_kh);
    cudaGetSymbolAddress((void**)&pvh, g_vh);
    cudaGetSymbolAddress((void**)&pcos, g_cos);
    cudaGetSymbolAddress((void**)&psin, g_sin);

    const int M = BB * SS;     // 4096
    const int K = HH;          // 2048

    // RoPE table + fused operand conversion
    rope_table<<<SS, 64>>>(pcos, psin);
    conv_all<<<18432, 256>>>(hs, q_w, k_w, v_w, o_w, hsh, qkvw, owh);

    cudaFuncSetAttribute(gemm_qkv, cudaFuncAttributeMaxDynamicSharedMemorySize,
                         QKV_SMEM);
    cudaFuncSetAttribute(gemm_fp16, cudaFuncAttributeMaxDynamicSharedMemorySize,
                         GS_SMEM);

    // fused QKV projection + rmsnorm + RoPE + fp16 emit (one GEMM)
    gemm_qkv<<<dim3(NQKV / 128, M / 128), 512, QKV_SMEM>>>(
        hsh, qkvw, qn, kn, pcos, psin, pqh, pkh, pvh);

    // tensor-core causal flash attention (BM=64, 2 CTAs/SM)
    cudaFuncSetAttribute(flash_attn_tc, cudaFuncAttributeMaxDynamicSharedMemorySize,
                         FL_SMEM);
    flash_attn_tc<<<dim3(SS / 64, NH, BB), 128, FL_SMEM>>>(pqh, pkh, pvh, pah);

    // output projection (1-pass fp16)
    gemm_fp16<<<dim3(HH / 128, M / 128), 512, GS_SMEM>>>(pah, owh,
                                                         out, M, HH, K);
}